// round 13
// baseline (speedup 1.0000x reference)
#include <cuda_runtime.h>
#include <math.h>

#define H      64
#define NFINE  (1 << 20)          // fine grid intervals over [0,1]
#define NC     (1 << 11)          // coarse grid intervals (= cubic cells)
#define NCTOT  (NC + 3)           // coarse entries: x = (idx-1)/NC
#define RSH    9                  // log2(NFINE/NC) = fine points per cell (512)
#define ZSH    13                 // log2(z-bucket count)
#define ZB     (1 << ZSH)         // z buckets -> 16 KB uint16 map (L1-resident)
#define MONO   1e-3f
#define GRID_BUILD 148            // one block per SM: co-residency guaranteed

__device__ float g_w2t[H * H];    // g_w2t[i*64+j] = exp(pw2[j][i])  (transposed)
__device__ float g_w1[H], g_b1[H], g_b2[H], g_w3[H], g_b3s;
__device__ float g_Ac[NCTOT];     // raw A at coarse grid (+/-1 pad): 8 KB
__device__ float4 g_CF[NC];       // u-scaled normalized cubic coeffs: 32 KB
__device__ float  g_TS[NC + 1];   // cell-start T values (== CF[c].x bits): 8 KB
__device__ float  g_NRB[NC];      // -1 / CF[c].y  (chord slope recip): 8 KB
__device__ unsigned short g_map[ZB]; // z-bucket -> max cell c with TS[c] <= k/ZB

// grid-barrier state (zero-initialized; reset by last block each launch)
__device__ unsigned g_barA, g_barB, g_done;

__device__ __forceinline__ float sigmoidf(float x) {
    return 1.0f / (1.0f + expf(-x));
}

__device__ __forceinline__ void grid_barrier(unsigned* ctr) {
    __syncthreads();
    if (threadIdx.x == 0) {
        __threadfence();                       // release phase data
        atomicAdd(ctr, 1u);
        volatile unsigned* v = ctr;
        while (*v < (unsigned)GRID_BUILD) __nanosleep(64);
    }
    __syncthreads();
}

// ---------------------------------------------------------------------------
// Fused build kernel: phase A (weight prep) -> barrier -> phase B (coarse
// network eval, warp-per-point) -> barrier -> phase C (cell coeffs + recip +
// z-bucket map). One launch instead of three (T_ovh ~5K cyc per launch).
// 148 blocks = 1/SM guaranteed resident, so the spin barrier cannot deadlock.
// ---------------------------------------------------------------------------
__global__ void __launch_bounds__(256, 1)
build_kernel(const float* __restrict__ pw1, const float* __restrict__ b1,
             const float* __restrict__ pw2, const float* __restrict__ b2,
             const float* __restrict__ pw3, const float* __restrict__ b3) {
    int tid = threadIdx.x;
    int e   = blockIdx.x * 256 + tid;

    // ---- Phase A: exponentiate + transpose weights (distributed) ----
    if (e < H * H) {
        int j = e >> 6, i = e & 63;
        g_w2t[i * H + j] = expf(pw2[e]);
    }
    if (e < H) {
        g_w1[e] = expf(pw1[e]);
        g_b1[e] = b1[e];
        g_b2[e] = b2[e];
        g_w3[e] = expf(pw3[e]);
    }
    if (e == 0) g_b3s = b3[0];

    grid_barrier(&g_barA);

    // ---- Phase B: coarse eval A(x), ONE WARP PER POINT (loop over grid) ----
    {
        int lane   = tid & 31;
        int nwarps = (GRID_BUILD * 256) >> 5;             // 1184
        for (int p = e >> 5; p < NCTOT; p += nwarps) {
            float x = (float)(p - 1) * (1.0f / (float)NC);

            float h1a = sigmoidf(fmaf(__ldg(&g_w1[lane]),      x, __ldg(&g_b1[lane])));
            float h1b = sigmoidf(fmaf(__ldg(&g_w1[lane + 32]), x, __ldg(&g_b1[lane + 32])));

            float acc0 = __ldg(&g_b2[2 * lane]);
            float acc1 = __ldg(&g_b2[2 * lane + 1]);
#pragma unroll
            for (int i = 0; i < 32; i++) {
                float  hv = __shfl_sync(0xffffffffu, h1a, i);
                float2 w  = __ldg(reinterpret_cast<const float2*>(&g_w2t[i * H + 2 * lane]));
                acc0 = fmaf(w.x, hv, acc0);
                acc1 = fmaf(w.y, hv, acc1);
            }
#pragma unroll
            for (int i = 0; i < 32; i++) {
                float  hv = __shfl_sync(0xffffffffu, h1b, i);
                float2 w  = __ldg(reinterpret_cast<const float2*>(&g_w2t[(i + 32) * H + 2 * lane]));
                acc0 = fmaf(w.x, hv, acc0);
                acc1 = fmaf(w.y, hv, acc1);
            }
            float part = fmaf(sigmoidf(acc0), __ldg(&g_w3[2 * lane]),
                              sigmoidf(acc1) * __ldg(&g_w3[2 * lane + 1]));
#pragma unroll
            for (int o = 16; o; o >>= 1) part += __shfl_xor_sync(0xffffffffu, part, o);

            if (lane == 0) g_Ac[p] = sigmoidf(part + g_b3s) + MONO * x;
        }
    }

    grid_barrier(&g_barB);

    // ---- Phase C: per-cell u-scaled coeffs + chord recip + bucket map ----
    if (e < NC) {
        int ci = e;
        const float a0      = g_Ac[1];
        const float a1      = g_Ac[1 + NC];
        const float inv_den = 1.0f / (a1 - a0);
        float P0 = g_Ac[ci];
        float P1 = g_Ac[ci + 1];
        float P2 = g_Ac[ci + 2];
        float P3 = g_Ac[ci + 3];
        float c1 = 0.5f * (P2 - P0);
        float c2 = P0 - 2.5f * P1 + 2.0f * P2 - 0.5f * P3;
        float c3 = 1.5f * (P1 - P2) + 0.5f * (P3 - P0);
        // u-units: t = u/512; divisions by pow2 are exact
        float a  = (P1 - a0) * inv_den;
        float bu = (c1 * inv_den) * (1.0f / 512.0f);
        float cu = (c2 * inv_den) * (1.0f / 262144.0f);
        float du = (c3 * inv_den) * (1.0f / 134217728.0f);
        g_CF[ci]  = make_float4(a, bu, cu, du);
        g_TS[ci]  = a;                        // T at cell start; cell 0 -> exactly 0
        g_NRB[ci] = -1.0f / bu;               // c1 > 0 (monotone data) => bu > 0
        if (ci == NC - 1) g_TS[NC] = 1.0f;    // T(NFINE) pinned to 1

        // next cell's start value: same expression as its own a (bit-equal)
        float tnext = (ci == NC - 1) ? 1.0f : (P2 - a0) * inv_den;
        int k0 = (int)ceilf(a     * (float)ZB);   // exact: pow2 scale
        int k1 = (int)ceilf(tnext * (float)ZB);
        if (k0 < 0) k0 = 0;
        if (k1 > ZB) k1 = ZB;
        for (int k = k0; k < k1; k++) g_map[k] = (unsigned short)ci;
    }

    // ---- reset barrier counters for the next graph replay ----
    __syncthreads();
    if (threadIdx.x == 0) {
        __threadfence();
        unsigned old = atomicAdd(&g_done, 1u);
        if (old == (unsigned)GRID_BUILD - 1) {   // every block has passed both spins
            g_barA = 0; g_barB = 0; g_done = 0;
            __threadfence();
        }
    }
}

// T at integer fine offset u within a cell (u-scaled coeffs): 3 FMA.
// Bit-identical expression everywhere it is used.
__device__ __forceinline__ float horner_u(float4 cf, float u) {
    return fmaf(u, fmaf(u, fmaf(u, cf.w, cf.z), cf.y), cf.x);
}

// ---------------------------------------------------------------------------
// Search: division-free chord inversion, zero random L2 traffic, no MUFU.
// Bucket map -> cell (TS[ci] <= z < TS[ci+1] after short advance); seed
// u = (z - a) / b via precomputed -1/b; 3 chord iterations (convergence
// ratio ~ |cell curvature / slope| << 1); floor; then an exact adjust loop
// (0-1 iterations typical) restoring lo = max{u : T(u) <= z} -- the same
// result as the reference 20-step fine-grid bisection.
// out = ((ci*512 + lo) + 0.5) * 2^-20.
// ---------------------------------------------------------------------------
__device__ __forceinline__ float invert_one(float zi) {
    int k = (int)(zi * (float)ZB);               // exact floor: pow2 scale
    k = min(max(k, 0), ZB - 1);
    int ci = (int)__ldg(&g_map[k]);              // TS[ci] <= k/ZB <= zi
    while (ci < NC - 1 && __ldg(&g_TS[ci + 1]) <= zi) ci++;
    float4 cf  = __ldg(&g_CF[ci]);
    float  nrb = __ldg(&g_NRB[ci]);              // -1/b
    float u = (cf.x - zi) * nrb;                 // linear seed = (zi - a)/b
    u = fminf(fmaxf(u, 0.0f), 512.0f);
#pragma unroll
    for (int it = 0; it < 3; it++) {
        float Tu = horner_u(cf, u);
        u = fmaf(Tu - zi, nrb, u);               // u -= (T(u) - z)/b
    }
    u = fminf(fmaxf(u, 0.0f), 511.0f);           // NaN-safe: fmaxf(NaN,0)=0
    int ui = (int)u;
    while (ui > 0 && horner_u(cf, (float)ui) > zi) ui--;
    while (ui < 511 && horner_u(cf, (float)(ui + 1)) <= zi) ui++;
    int j = (ci << RSH) + ui;
    return (float)(2 * j + 1) * 0x1p-21f;        // (j + 0.5) * 2^-20, exact
}

__global__ void search_kernel(const float* __restrict__ z, float* __restrict__ out, int n) {
    int i = (blockIdx.x * blockDim.x + threadIdx.x) * 2;
    if (i + 1 < n) {
        float2 zv = *reinterpret_cast<const float2*>(z + i);
        float2 ov;
        ov.x = invert_one(zv.x);
        ov.y = invert_one(zv.y);
        *reinterpret_cast<float2*>(out + i) = ov;
    } else if (i < n) {
        out[i] = invert_one(z[i]);
    }
}

// ---------------------------------------------------------------------------
extern "C" void kernel_launch(void* const* d_in, const int* in_sizes, int n_in,
                              void* d_out, int out_size) {
    const float* z   = (const float*)d_in[0];
    const float* pw1 = (const float*)d_in[1];
    const float* b1  = (const float*)d_in[2];
    const float* pw2 = (const float*)d_in[3];
    const float* b2  = (const float*)d_in[4];
    const float* pw3 = (const float*)d_in[5];
    const float* b3  = (const float*)d_in[6];
    float* out = (float*)d_out;
    int n = in_sizes[0];

    build_kernel<<<GRID_BUILD, 256>>>(pw1, b1, pw2, b2, pw3, b3);
    int nq = (n + 1) / 2;
    search_kernel<<<(nq + 255) / 256, 256>>>(z, out, n);
}